// round 15
// baseline (speedup 1.0000x reference)
#include <cuda_runtime.h>
#include <cuda_fp16.h>
#include <cstdint>

// ---------------------------------------------------------------------------
// Problem constants  (R13 champion configuration; SMEM kept at 59.4KB so
// 3 CTAs/SM leave ~50KB of L1D for .ca x-window reuse)
// ---------------------------------------------------------------------------
#define OUT_N    8192
#define IN_K     8192
#define BATCH    64
#define TILE_N   128                  // W rows per CTA
#define KSPLIT   8
#define NGRPS    (OUT_N / TILE_N)     // 64
#define NSUB     16                   // k64 subchunks per CTA (k total 1024)
#define NCH      8                    // k128 scale-chunks per CTA
#define NTHREADS 256

#define RS          144               // 128B row + 16B pad (ldmatrix-clean)
#define W_BYTES     (TILE_N * RS)          // 18432
#define X_OFF       W_BYTES
#define X_BYTES     (BATCH * RS)           // 9216
#define STAGE_BYTES (W_BYTES + X_BYTES)    // 27648
#define SCALE_OFF   (2 * STAGE_BYTES)      // 55296
#define SCALE_BYTES (NCH * TILE_N * 4)     // 4096
#define SMEM_TOTAL  (SCALE_OFF + SCALE_BYTES)  // 59392 -> 3 CTAs/SM

// Static scratch: x converted to fp16 (1 MiB)
__device__ __half g_xh[BATCH * IN_K];

// ---------------------------------------------------------------------------
// PTX helpers (family-portable: ptxas target is sm_103, no tcgen05)
// ---------------------------------------------------------------------------
__device__ __forceinline__ void ldsm_x4(uint32_t& r0, uint32_t& r1, uint32_t& r2,
                                        uint32_t& r3, uint32_t addr) {
    asm volatile("ldmatrix.sync.aligned.m8n8.x4.shared.b16 {%0,%1,%2,%3}, [%4];"
                 : "=r"(r0), "=r"(r1), "=r"(r2), "=r"(r3) : "r"(addr));
}
__device__ __forceinline__ void mma_16816(float* c, uint32_t a0, uint32_t a1,
                                          uint32_t a2, uint32_t a3,
                                          uint32_t b0, uint32_t b1) {
    asm volatile(
        "mma.sync.aligned.m16n8k16.row.col.f32.f16.f16.f32 "
        "{%0,%1,%2,%3},{%4,%5,%6,%7},{%8,%9},{%0,%1,%2,%3};"
        : "+f"(c[0]), "+f"(c[1]), "+f"(c[2]), "+f"(c[3])
        : "r"(a0), "r"(a1), "r"(a2), "r"(a3), "r"(b0), "r"(b1));
}
// .ca: co-resident CTAs (same k-group) re-read identical x windows -> L1 hits
__device__ __forceinline__ void cp_async16_ca(uint32_t dst, const void* src) {
    asm volatile("cp.async.ca.shared.global [%0], [%1], 16;"
                 :: "r"(dst), "l"(src) : "memory");
}
__device__ __forceinline__ void cp_commit() {
    asm volatile("cp.async.commit_group;" ::: "memory");
}

// ---------------------------------------------------------------------------
// Kernel 1: convert x fp32->fp16 AND zero-init out.
// 256 blocks x 256 threads x 2 independent float4 (TLP + MLP balance).
// ---------------------------------------------------------------------------
__global__ __launch_bounds__(256) void prep_kernel(const float* __restrict__ x,
                                                   float* __restrict__ out) {
    int base = blockIdx.x * 512 + threadIdx.x;
    #pragma unroll
    for (int k = 0; k < 2; k++) {
        int i = base + k * 256;
        float4 v = reinterpret_cast<const float4*>(x)[i];
        __half2 h01 = __floats2half2_rn(v.x, v.y);
        __half2 h23 = __floats2half2_rn(v.z, v.w);
        uint2 o;
        o.x = *reinterpret_cast<uint32_t*>(&h01);
        o.y = *reinterpret_cast<uint32_t*>(&h23);
        reinterpret_cast<uint2*>(g_xh)[i] = o;
        reinterpret_cast<float4*>(out)[i] = make_float4(0.f, 0.f, 0.f, 0.f);
    }
}

// ---------------------------------------------------------------------------
// Kernel 2: int4-dequant GEMM (mma.sync), k64 subchunk pipeline, 3 CTAs/SM.
// Grid = 512 CTAs: bid & 63 = n-group (128 W rows), bid >> 6 = k-group.
// Warp layout 2(m) x 4(n): warp owns 32 batch rows x 32 output cols.
// ISSUE-INTERLEAVED pipeline: staging for sub+1 (dequant STS, x cp.async,
// pv LDG for sub+2) is folded INTO the 4-kt MMA loop so the volatile asm
// stream interleaves memory issue with mma latency shadows.
// ---------------------------------------------------------------------------
__global__ __launch_bounds__(NTHREADS, 3)
void dq_gemm_kernel(const int*   __restrict__ packed,
                    const float* __restrict__ scales,
                    float*       __restrict__ out)
{
    extern __shared__ __align__(16) char dsm[];
    const uint32_t sb = (uint32_t)__cvta_generic_to_shared(dsm);
    float* sScale = reinterpret_cast<float*>(dsm + SCALE_OFF);

    const int tid  = threadIdx.x;
    const int wid  = tid >> 5;
    const int lane = tid & 31;
    const int mh   = wid & 1;          // batch half
    const int ng   = wid >> 1;         // 32-col group
    const int n0   = (blockIdx.x & 63) * TILE_N;
    const int kg   = blockIdx.x >> 6;  // 0..7
    const int ks0  = kg * NSUB;        // global k64-subchunk base

    float acc[2][4][4];
    #pragma unroll
    for (int m = 0; m < 2; m++)
        #pragma unroll
        for (int n = 0; n < 4; n++)
            #pragma unroll
            for (int j = 0; j < 4; j++) acc[m][n][j] = 0.f;

    const uint4* pk4 = reinterpret_cast<const uint4*>(packed); // row stride 1024
    const uint32_t c1032b = 0x64086408u;                       // half2(1032,1032)
    const __half2 c1032 = *reinterpret_cast<const __half2*>(&c1032b);

    // per-thread staging coordinates (fixed across subs)
    const int srow = tid >> 3;                   // used with +128-row offset
    const int skv  = tid & 7;

    // ---- stage the scale table once: [NCH][TILE_N], float4-vectorized -----
    {
        int row = tid >> 1;                      // 0..127
        int c4  = tid & 1;
        float4 f = *reinterpret_cast<const float4*>(
            scales + (size_t)(n0 + row) * 64 + kg * NCH + c4 * 4);
        sScale[(c4 * 4 + 0) * TILE_N + row] = f.x;
        sScale[(c4 * 4 + 1) * TILE_N + row] = f.y;
        sScale[(c4 * 4 + 2) * TILE_N + row] = f.z;
        sScale[(c4 * 4 + 3) * TILE_N + row] = f.w;
    }

    // ---- packed-W register prefetch (one k64 sub = 1024 uint4 = 4/thread) -
    uint4 pv[4];
    auto prefetch_all = [&](int ks) {
        #pragma unroll
        for (int j = 0; j < 4; j++) {
            int row = srow + (j << 5);           // (tid + j*256) >> 3
            pv[j] = pk4[(size_t)(n0 + row) * 1024 + ks * 8 + skv];
        }
    };

    // ---- x tile cp.async, full (prologue only) ----------------------------
    auto stage_x_all = [&](int ks, int s) {
        const uint32_t xb = sb + s * STAGE_BYTES + X_OFF;
        #pragma unroll
        for (int j = 0; j < 2; j++) {
            int u = tid + (j << 8);
            int b = u >> 3, kv = u & 7;
            cp_async16_ca(xb + b * RS + kv * 16,
                          &g_xh[(size_t)b * IN_K + ks * 64 + kv * 8]);
        }
        cp_commit();
    };

    // dequant part j of subchunk sub -> W buffer s (1 x STS.128 / thread)
    auto dequant_part = [&](int s, int sub, int j) {
        const uint32_t stage = sb + s * STAGE_BYTES;
        const int lch = sub >> 1;
        int row = srow + (j << 5);
        __half2 s2 = __float2half2_rn(sScale[lch * TILE_N + row]);
        uint32_t w[4] = { pv[j].x, pv[j].y, pv[j].z, pv[j].w };
        uint32_t o[4];
        #pragma unroll
        for (int q = 0; q < 4; q++) {
            uint32_t t = ((w[q] * 0x1001u) & 0x000F000Fu) | 0x64006400u;
            __half2 hv = __hmul2(__hsub2(*reinterpret_cast<__half2*>(&t), c1032), s2);
            o[q] = *reinterpret_cast<uint32_t*>(&hv);
        }
        asm volatile("st.shared.v4.b32 [%0], {%1,%2,%3,%4};"
                     :: "r"(stage + row * RS + skv * 16),
                        "r"(o[0]), "r"(o[1]), "r"(o[2]), "r"(o[3]) : "memory");
    };

    // ---- prologue ---------------------------------------------------------
    prefetch_all(ks0);             // pv = packed[sub 0]
    stage_x_all(ks0, 0);           // x[0] in flight
    __syncthreads();               // sScale visible to all
    #pragma unroll
    for (int j = 0; j < 4; j++) dequant_part(0, 0, j);   // W[0] -> stage 0
    prefetch_all(ks0 + 1);         // pv = packed[sub 1]

    // Invariant at iteration entry (sub, s = sub&1):
    //   x[sub] cp.async group pending-or-done; W[sub] STS issued into stage s;
    //   pv = packed[sub+1].
    for (int sub = 0; sub < NSUB; sub++) {
        const int s = sub & 1;
        const bool doStage = (sub + 1 < NSUB);
        const bool doPre   = (sub + 2 < NSUB);

        asm volatile("cp.async.wait_group 0;" ::: "memory");  // x[sub] landed
        __syncthreads();     // W[sub]/x[sub] visible; stage s^1 free

        const uint32_t wbase = sb + s * STAGE_BYTES;
        const uint32_t xbase = wbase + X_OFF;
        const uint32_t xnb   = sb + (s ^ 1) * STAGE_BYTES + X_OFF;

        // ---- fused MMA(sub) + staging(sub+1/sub+2), interleaved per kt ----
        #pragma unroll
        for (int kt = 0; kt < 4; kt++) {
            uint32_t b[4][2];             // [nt][b0,b1]
            #pragma unroll
            for (int np = 0; np < 2; np++) {
                int br = ng * 32 + np * 16 + ((lane >> 4) & 1) * 8 + (lane & 7);
                int bc = kt * 16 + ((lane >> 3) & 1) * 8;
                ldsm_x4(b[np*2][0], b[np*2][1], b[np*2+1][0], b[np*2+1][1],
                        wbase + (uint32_t)(br * RS + bc * 2));
            }
            #pragma unroll
            for (int mt = 0; mt < 2; mt++) {
                uint32_t a0, a1, a2, a3;
                int ar = mh * 32 + mt * 16 + (lane & 15);
                int ac = kt * 16 + (lane >> 4) * 8;
                ldsm_x4(a0, a1, a2, a3, xbase + (uint32_t)(ar * RS + ac * 2));
                #pragma unroll
                for (int nt = 0; nt < 4; nt++)
                    mma_16816(acc[mt][nt], a0, a1, a2, a3, b[nt][0], b[nt][1]);
            }

            // staging slice kt: fills the mma/ldsm latency shadow
            if (doStage) {
                dequant_part(s ^ 1, sub + 1, kt);         // reads pv[kt]
                if (kt < 2) {                             // x[sub+1], 2 slices
                    int u = tid + (kt << 8);
                    int bb = u >> 3, kv = u & 7;
                    cp_async16_ca(xnb + bb * RS + kv * 16,
                                  &g_xh[(size_t)bb * IN_K + (ks0 + sub + 1) * 64 + kv * 8]);
                    if (kt == 1) cp_commit();
                }
                if (doPre) {                              // pv[kt] <- packed[sub+2]
                    int row = srow + (kt << 5);           // (after dequant read)
                    pv[kt] = pk4[(size_t)(n0 + row) * 1024 + (ks0 + sub + 2) * 8 + skv];
                }
            }
        }
    }

    // ---- epilogue: vectorized float2 atomics (k-split merge) --------------
    #pragma unroll
    for (int mt = 0; mt < 2; mt++) {
        #pragma unroll
        for (int nt = 0; nt < 4; nt++) {
            int m = mh * 32 + mt * 16 + (lane >> 2);
            int n = n0 + ng * 32 + nt * 8 + (lane & 3) * 2;
            atomicAdd(reinterpret_cast<float2*>(&out[(size_t)m * OUT_N + n]),
                      make_float2(acc[mt][nt][0], acc[mt][nt][1]));
            atomicAdd(reinterpret_cast<float2*>(&out[(size_t)(m + 8) * OUT_N + n]),
                      make_float2(acc[mt][nt][2], acc[mt][nt][3]));
        }
    }
}

// ---------------------------------------------------------------------------
extern "C" void kernel_launch(void* const* d_in, const int* in_sizes, int n_in,
                              void* d_out, int out_size) {
    const float* x      = (const float*)d_in[0];
    const int*   packed = (const int*)d_in[1];
    const float* scales = (const float*)d_in[2];
    float*       out    = (float*)d_out;

    cudaFuncSetAttribute(dq_gemm_kernel,
                         cudaFuncAttributeMaxDynamicSharedMemorySize, SMEM_TOTAL);

    prep_kernel<<<256, 256>>>(x, out);
    dq_gemm_kernel<<<NGRPS * KSPLIT, NTHREADS, SMEM_TOTAL>>>(packed, scales, out);
}

// round 16
// speedup vs baseline: 1.6330x; 1.6330x over previous
#include <cuda_runtime.h>
#include <cuda_fp16.h>
#include <cstdint>

// ---------------------------------------------------------------------------
// Problem constants  (R13 champion configuration)
// ---------------------------------------------------------------------------
#define OUT_N    8192
#define IN_K     8192
#define BATCH    64
#define TILE_N   128                  // W rows per CTA
#define KSPLIT   8
#define NGRPS    (OUT_N / TILE_N)     // 64
#define NSUB     16                   // k64 subchunks per CTA (k total 1024)
#define NCH      8                    // k128 scale-chunks per CTA
#define NTHREADS 256

// SMEM layout (bytes). Rows hold 64 halfs = 128 B, padded stride 144 B
// (odd multiple of 16 B -> conflict-free ldmatrix over 8-row groups).
// 59.4KB total -> 3 CTAs/SM (178KB), leaving ~50KB L1D for .ca reuse.
#define RS          144
#define W_BYTES     (TILE_N * RS)          // 18432
#define X_OFF       W_BYTES
#define X_BYTES     (BATCH * RS)           // 9216
#define STAGE_BYTES (W_BYTES + X_BYTES)    // 27648
#define SCALE_OFF   (2 * STAGE_BYTES)      // 55296
#define SCALE_BYTES (NCH * TILE_N * 4)     // 4096
#define SMEM_TOTAL  (SCALE_OFF + SCALE_BYTES)  // 59392

// Static scratch: x converted to fp16 (1 MiB)
__device__ __half g_xh[BATCH * IN_K];

// ---------------------------------------------------------------------------
// PTX helpers (family-portable: ptxas target is sm_103, no tcgen05)
// ---------------------------------------------------------------------------
__device__ __forceinline__ void ldsm_x4(uint32_t& r0, uint32_t& r1, uint32_t& r2,
                                        uint32_t& r3, uint32_t addr) {
    asm volatile("ldmatrix.sync.aligned.m8n8.x4.shared.b16 {%0,%1,%2,%3}, [%4];"
                 : "=r"(r0), "=r"(r1), "=r"(r2), "=r"(r3) : "r"(addr));
}
__device__ __forceinline__ void mma_16816(float* c, uint32_t a0, uint32_t a1,
                                          uint32_t a2, uint32_t a3,
                                          uint32_t b0, uint32_t b1) {
    asm volatile(
        "mma.sync.aligned.m16n8k16.row.col.f32.f16.f16.f32 "
        "{%0,%1,%2,%3},{%4,%5,%6,%7},{%8,%9},{%0,%1,%2,%3};"
        : "+f"(c[0]), "+f"(c[1]), "+f"(c[2]), "+f"(c[3])
        : "r"(a0), "r"(a1), "r"(a2), "r"(a3), "r"(b0), "r"(b1));
}
// .ca: co-resident CTAs (same k-group) re-read identical x windows -> L1 hits
__device__ __forceinline__ void cp_async16_ca(uint32_t dst, const void* src) {
    asm volatile("cp.async.ca.shared.global [%0], [%1], 16;"
                 :: "r"(dst), "l"(src) : "memory");
}
__device__ __forceinline__ void cp_commit() {
    asm volatile("cp.async.commit_group;" ::: "memory");
}

// ---------------------------------------------------------------------------
// Kernel 1: convert x fp32->fp16 AND zero-init out.
// 256 blocks x 256 threads x 2 independent float4 (measured: ~2.5us total
// overhead vs ~5.0us for the 128-block variant).
// ---------------------------------------------------------------------------
__global__ __launch_bounds__(256) void prep_kernel(const float* __restrict__ x,
                                                   float* __restrict__ out) {
    int base = blockIdx.x * 512 + threadIdx.x;
    #pragma unroll
    for (int k = 0; k < 2; k++) {
        int i = base + k * 256;
        float4 v = reinterpret_cast<const float4*>(x)[i];
        __half2 h01 = __floats2half2_rn(v.x, v.y);
        __half2 h23 = __floats2half2_rn(v.z, v.w);
        uint2 o;
        o.x = *reinterpret_cast<uint32_t*>(&h01);
        o.y = *reinterpret_cast<uint32_t*>(&h23);
        reinterpret_cast<uint2*>(g_xh)[i] = o;
        reinterpret_cast<float4*>(out)[i] = make_float4(0.f, 0.f, 0.f, 0.f);
    }
}

// ---------------------------------------------------------------------------
// Kernel 2: int4-dequant GEMM (mma.sync), k64 subchunk pipeline, 3 CTAs/SM.
// Grid = 512 CTAs: bid & 63 = n-group (128 W rows), bid >> 6 = k-group.
// Warp layout 2(m) x 4(n): warp owns 32 batch rows x 32 output cols.
// Phase shift (R9/R10 scheme): iter sub stages subchunk sub+1 as one
// CONTIGUOUS block before MMA(sub) -- scoreboard overlaps it with the MMA
// phase across the barrier interval (R15 proved manual interleaving loses).
// ---------------------------------------------------------------------------
__global__ __launch_bounds__(NTHREADS, 3)
void dq_gemm_kernel(const int*   __restrict__ packed,
                    const float* __restrict__ scales,
                    float*       __restrict__ out)
{
    extern __shared__ __align__(16) char dsm[];
    const uint32_t sb = (uint32_t)__cvta_generic_to_shared(dsm);
    float* sScale = reinterpret_cast<float*>(dsm + SCALE_OFF);

    const int tid  = threadIdx.x;
    const int wid  = tid >> 5;
    const int lane = tid & 31;
    const int mh   = wid & 1;          // batch half
    const int ng   = wid >> 1;         // 32-col group
    const int n0   = (blockIdx.x & 63) * TILE_N;
    const int kg   = blockIdx.x >> 6;  // 0..7
    const int ks0  = kg * NSUB;        // global k64-subchunk base

    float acc[2][4][4];
    #pragma unroll
    for (int m = 0; m < 2; m++)
        #pragma unroll
        for (int n = 0; n < 4; n++)
            #pragma unroll
            for (int j = 0; j < 4; j++) acc[m][n][j] = 0.f;

    const uint4* pk4 = reinterpret_cast<const uint4*>(packed); // row stride 1024
    const uint32_t c1032b = 0x64086408u;                       // half2(1032,1032)
    const __half2 c1032 = *reinterpret_cast<const __half2*>(&c1032b);

    // ---- stage the scale table once: [NCH][TILE_N], float4-vectorized -----
    {
        int row = tid >> 1;                      // 0..127
        int c4  = tid & 1;                       // which float4 of the row
        float4 f = *reinterpret_cast<const float4*>(
            scales + (size_t)(n0 + row) * 64 + kg * NCH + c4 * 4);
        sScale[(c4 * 4 + 0) * TILE_N + row] = f.x;
        sScale[(c4 * 4 + 1) * TILE_N + row] = f.y;
        sScale[(c4 * 4 + 2) * TILE_N + row] = f.z;
        sScale[(c4 * 4 + 3) * TILE_N + row] = f.w;
    }

    // ---- packed-W register prefetch (one k64 sub = 1024 uint4 = 4/thread) -
    uint4 pv[4];
    auto prefetch = [&](int ks) {
        #pragma unroll
        for (int j = 0; j < 4; j++) {
            int u = tid + (j << 8);                  // 0..1023
            int row = u >> 3, kv = u & 7;
            pv[j] = pk4[(size_t)(n0 + row) * 1024 + ks * 8 + kv];
        }
    };

    // ---- x tile cp.async (512 x 16B units = 2/thread), L1-cached ----------
    auto stage_x = [&](int ks, int s) {
        const uint32_t xb = sb + s * STAGE_BYTES + X_OFF;
        #pragma unroll
        for (int j = 0; j < 2; j++) {
            int u = tid + (j << 8);                  // 0..511
            int b = u >> 3, kv = u & 7;
            cp_async16_ca(xb + b * RS + kv * 16,
                          &g_xh[(size_t)b * IN_K + ks * 64 + kv * 8]);
        }
        cp_commit();
    };

    // dequant pv (subchunk sub) -> W buffer s (4 x STS.128 / thread)
    auto dequant_sts = [&](int s, int sub) {
        const uint32_t stage = sb + s * STAGE_BYTES;
        const int lch = sub >> 1;                    // k128 scale chunk
        #pragma unroll
        for (int j = 0; j < 4; j++) {
            int u = tid + (j << 8);
            int row = u >> 3, kv = u & 7;
            __half2 s2 = __float2half2_rn(sScale[lch * TILE_N + row]);
            uint32_t w[4] = { pv[j].x, pv[j].y, pv[j].z, pv[j].w };
            uint32_t o[4];
            #pragma unroll
            for (int q = 0; q < 4; q++) {
                uint32_t t = ((w[q] * 0x1001u) & 0x000F000Fu) | 0x64006400u;
                __half2 hv = __hmul2(__hsub2(*reinterpret_cast<__half2*>(&t), c1032), s2);
                o[q] = *reinterpret_cast<uint32_t*>(&hv);
            }
            asm volatile("st.shared.v4.b32 [%0], {%1,%2,%3,%4};"
                         :: "r"(stage + row * RS + kv * 16),
                            "r"(o[0]), "r"(o[1]), "r"(o[2]), "r"(o[3]) : "memory");
        }
    };

    // ---- prologue ---------------------------------------------------------
    prefetch(ks0);           // pv = packed[sub 0]
    stage_x(ks0, 0);         // x[0] in flight
    __syncthreads();         // sScale visible to all
    dequant_sts(0, 0);       // W[0] STS -> stage 0
    prefetch(ks0 + 1);       // pv = packed[sub 1]

    // Invariant at iteration entry (sub, s = sub&1):
    //   x[sub] cp.async group pending; W[sub] STS issued into stage s;
    //   pv = packed[sub+1].
    for (int sub = 0; sub < NSUB; sub++) {
        const int s = sub & 1;

        asm volatile("cp.async.wait_group 0;" ::: "memory");  // x[sub] landed
        __syncthreads();     // W[sub]/x[sub] visible; stage s^1 free

        if (sub + 1 < NSUB) {
            stage_x(ks0 + sub + 1, s ^ 1);       // x[sub+1] in flight
            dequant_sts(s ^ 1, sub + 1);         // W[sub+1] STS (other buffer)
            if (sub + 2 < NSUB) prefetch(ks0 + sub + 2);  // LDGs overlap MMA
        }

        // ---- MMA(sub): 4 k16 tiles, warp tile 32(m) x 32(n), stage s ------
        const uint32_t wbase = sb + s * STAGE_BYTES;
        const uint32_t xbase = wbase + X_OFF;
        #pragma unroll
        for (int kt = 0; kt < 4; kt++) {
            uint32_t b[4][2];             // [nt][b0,b1]
            #pragma unroll
            for (int np = 0; np < 2; np++) {
                int br = ng * 32 + np * 16 + ((lane >> 4) & 1) * 8 + (lane & 7);
                int bc = kt * 16 + ((lane >> 3) & 1) * 8;
                ldsm_x4(b[np*2][0], b[np*2][1], b[np*2+1][0], b[np*2+1][1],
                        wbase + (uint32_t)(br * RS + bc * 2));
            }
            #pragma unroll
            for (int mt = 0; mt < 2; mt++) {
                uint32_t a0, a1, a2, a3;
                int ar = mh * 32 + mt * 16 + (lane & 15);
                int ac = kt * 16 + (lane >> 4) * 8;
                ldsm_x4(a0, a1, a2, a3, xbase + (uint32_t)(ar * RS + ac * 2));
                #pragma unroll
                for (int nt = 0; nt < 4; nt++)
                    mma_16816(acc[mt][nt], a0, a1, a2, a3, b[nt][0], b[nt][1]);
            }
        }
    }

    // ---- epilogue: vectorized float2 atomics (k-split merge) --------------
    #pragma unroll
    for (int mt = 0; mt < 2; mt++) {
        #pragma unroll
        for (int nt = 0; nt < 4; nt++) {
            int m = mh * 32 + mt * 16 + (lane >> 2);
            int n = n0 + ng * 32 + nt * 8 + (lane & 3) * 2;
            atomicAdd(reinterpret_cast<float2*>(&out[(size_t)m * OUT_N + n]),
                      make_float2(acc[mt][nt][0], acc[mt][nt][1]));
            atomicAdd(reinterpret_cast<float2*>(&out[(size_t)(m + 8) * OUT_N + n]),
                      make_float2(acc[mt][nt][2], acc[mt][nt][3]));
        }
    }
}

// ---------------------------------------------------------------------------
extern "C" void kernel_launch(void* const* d_in, const int* in_sizes, int n_in,
                              void* d_out, int out_size) {
    const float* x      = (const float*)d_in[0];
    const int*   packed = (const int*)d_in[1];
    const float* scales = (const float*)d_in[2];
    float*       out    = (float*)d_out;

    cudaFuncSetAttribute(dq_gemm_kernel,
                         cudaFuncAttributeMaxDynamicSharedMemorySize, SMEM_TOTAL);

    prep_kernel<<<256, 256>>>(x, out);
    dq_gemm_kernel<<<NGRPS * KSPLIT, NTHREADS, SMEM_TOTAL>>>(packed, scales, out);
}